// round 7
// baseline (speedup 1.0000x reference)
#include <cuda_runtime.h>
#include <stdint.h>

#define Nn 4096
#define Cc 10
#define LMAX 128
#define S1 0.73105857863000489f      // sigmoid(1.0) in fp32
#define TPB 128                       // threads per block
#define BPS 8                         // blocks per SM (forced via launch_bounds)

// ---------------- scratch (static device globals; no allocation) ------------
__device__ int   g_colcnt[Nn];            // masked in-neighbor count of column k
__device__ int   g_colidx[Nn * LMAX];     // RANKS of masked in-neighbors of column k
__device__ int   g_deg[Nn];               // out-degree (masked rows only)
__device__ int   g_rowidx[Nn * LMAX];     // out-neighbor node ids (masked rows only)
__device__ unsigned char g_diag[Nn];
__device__ float g_mask[Nn];
__device__ int   g_rank[Nn];              // dense rank among masked nodes, -1 if unmasked
__device__ float g_wp[Nn];                // exp(-pos[p]) * m[p]
__device__ float g_cep[Nn];               // per-node CE contribution
__device__ float g_Eq[Cc * Nn];           // exp(preds[q,i]) * m[q]
__device__ float g_Qs[Cc * Cc];           // sum_{q in class j, masked} exp(preds[q,i])
__device__ float g_T[Cc * Cc];            // correction part of pairwise sum
__device__ float g_Si[Cc * Cc];           // S_inter (masked)
__device__ float g_Sc[Cc * Cc];           // S_corr  (masked)
__device__ float g_Ncnt[Cc];
__device__ float g_Sdeg[Cc];
__device__ float g_W0[Cc];                // sum_{p in i, masked} wp*v0
__device__ int   g_qn;                    // number of masked nodes
__device__ int   g_qlist[Nn];             // masked node ids by rank
__device__ int   g_qlabel[Nn];            // their labels
// software grid barriers (self-resetting at end of each replay)
__device__ int          g_cnt1, g_cnt2, g_cnt3;
__device__ volatile int g_flag1, g_flag2;

__global__ void __launch_bounds__(TPB, BPS)
k_fused(const float* __restrict__ preds,
        const int* __restrict__ labels,
        const unsigned int* __restrict__ mask,
        const unsigned int* __restrict__ adj,
        float* __restrict__ out) {
    __shared__ unsigned int scnt[Nn];     // 16KB rank-indexed counters
    __shared__ int   s_nbr[LMAX];
    __shared__ float sT[Cc], sSi[Cc], sSc[Cc];
    __shared__ float sred[TPB];
    __shared__ int   s_wsum[TPB / 32];
    __shared__ int   s_last;

    const int tid = threadIdx.x, bi = blockIdx.x;
    const int lane = tid & 31, wid = tid >> 5;
    const int nblk = gridDim.x;
    const int t = bi * TPB + tid;

    // ================= Phase A: per-node (no atomics) =================
    if (t < Nn) {
        g_colcnt[t] = 0; g_deg[t] = 0; g_diag[t] = 0;
        if (t < Cc * Cc) { g_T[t] = 0.f; g_Si[t] = 0.f; g_Sc[t] = 0.f; g_Qs[t] = 0.f; }
        if (t < Cc) { g_Ncnt[t] = 0.f; g_Sdeg[t] = 0.f; g_W0[t] = 0.f; }

        float m = (mask[t] != 0u) ? 1.f : 0.f;   // 4-byte bool (i32 1 or f32 bits)
        g_mask[t] = m;
        float r[Cc], E[Cc], se = 0.f;
#pragma unroll
        for (int c = 0; c < Cc; c++) {
            r[c] = preds[t * Cc + c];
            E[c] = __expf(r[c]);
            se += E[c];
        }
        int l = labels[t];
        g_cep[t] = __logf(se) - r[l];            // -log softmax[l]
        g_wp[t] = __fdividef(m, E[l]);           // exp(-r[l]) * m
#pragma unroll
        for (int i = 0; i < Cc; i++) g_Eq[i * Nn + t] = E[i] * m;
    }

    // ===== Barrier 1: last-arriving block runs the rank prefix scan =====
    __syncthreads();
    if (tid == 0) { __threadfence(); s_last = (atomicAdd(&g_cnt1, 1) == nblk - 1); }
    __syncthreads();
    if (s_last) {
        __threadfence();
        int base = tid * 32;                      // 128 threads x 32 nodes = 4096
        unsigned mv = 0; int cnt = 0;
#pragma unroll
        for (int j = 0; j < 32; j++) {
            if (__ldcg(&g_mask[base + j]) != 0.f) { mv |= 1u << j; cnt++; }
        }
        int inc = cnt;
#pragma unroll
        for (int o = 1; o < 32; o <<= 1) {
            int y = __shfl_up_sync(0xFFFFFFFFu, inc, o);
            if (lane >= o) inc += y;
        }
        if (lane == 31) s_wsum[wid] = inc;
        __syncthreads();
        int woff = 0;
#pragma unroll
        for (int k = 0; k < TPB / 32; k++) if (k < wid) woff += s_wsum[k];
        int rk = woff + inc - cnt;                // exclusive prefix
#pragma unroll
        for (int j = 0; j < 32; j++) {
            int pp = base + j;
            if ((mv >> j) & 1u) {
                g_rank[pp] = rk; g_qlist[rk] = pp; g_qlabel[rk] = labels[pp]; rk++;
            } else g_rank[pp] = -1;
        }
        if (tid == TPB - 1) g_qn = rk;
        __syncthreads();
        if (tid == 0) { __threadfence(); g_flag1 = 1; }
    } else {
        if (tid == 0) { while (g_flag1 == 0) __nanosleep(64); __threadfence(); }
        __syncthreads();
    }
    const int qn = __ldcg(&g_qn);

    // ================= Phase B: warp-per-masked-row build =================
    {
        int r = bi * (TPB / 32) + wid;            // 4*nblk warps >= qn
        if (r < qn) {
            int p = __ldcg(&g_qlist[r]);
            const uint4* rowp = (const uint4*)(adj + (size_t)p * Nn);
#pragma unroll
            for (int it = 0; it < 4; it++) {
                uint4 a[8];
#pragma unroll
                for (int s = 0; s < 8; s++) a[s] = rowp[lane + (it * 8 + s) * 32];
#pragma unroll
                for (int s = 0; s < 8; s++) {
                    if (a[s].x | a[s].y | a[s].z | a[s].w) {
                        int i4 = lane + (it * 8 + s) * 32;
                        unsigned parts[4] = {a[s].x, a[s].y, a[s].z, a[s].w};
#pragma unroll
                        for (int u = 0; u < 4; u++) {
                            if (parts[u]) {
                                int kk = i4 * 4 + u;
                                int ri = atomicAdd(&g_deg[p], 1);
                                if (ri < LMAX) g_rowidx[p * LMAX + ri] = kk;
                                int ci = atomicAdd(&g_colcnt[kk], 1);
                                if (ci < LMAX) g_colidx[kk * LMAX + ci] = r;
                                if (p == kk) g_diag[p] = 1;
                            }
                        }
                    }
                }
            }
        }
    }

    // ===== Barrier 2 (full) =====
    __syncthreads();
    if (tid == 0) {
        __threadfence();
        if (atomicAdd(&g_cnt2, 1) == nblk - 1) { __threadfence(); g_flag2 = 1; }
        else { while (g_flag2 == 0) __nanosleep(64); }
        __threadfence();
    }
    __syncthreads();

    // ================= Phase C: block-per-masked-row pairwise =================
    for (int r = bi; r < qn; r += nblk) {
        int p  = __ldcg(&g_qlist[r]);
        int cp = __ldcg(&g_qlabel[r]);
        for (int i = tid; i < qn; i += TPB) scnt[i] = 0u;
        if (tid < Cc) { sT[tid] = 0.f; sSi[tid] = 0.f; sSc[tid] = 0.f; }
        int degi = __ldcg(&g_deg[p]);
        int dp = min(degi, LMAX);
        for (int i = tid; i < dp; i += TPB) s_nbr[i] = __ldcg(&g_rowidx[p * LMAX + i]);
        __syncthreads();

        for (int i = wid; i < dp; i += TPB / 32) {
            int k = s_nbr[i];
            int c = min(__ldcg(&g_colcnt[k]), LMAX);
            for (int j = lane; j < c; j += 32)
                atomicAdd(&scnt[__ldcg(&g_colidx[k * LMAX + j])], 1u);
        }
        for (int i = tid; i < dp; i += TPB) {
            int q = s_nbr[i];
            int rq = __ldcg(&g_rank[q]);
            if (rq >= 0 && !__ldcg(&g_diag[q])) atomicAdd(&scnt[rq], 65536u);
        }
        __syncthreads();

        float wp = __ldcg(&g_wp[p]);
        float degp = (float)degi;
        float v0 = 1.0f / (1.0f + __expf(1.0f + S1 * degp));   // 1 - sigmoid
        const float* eqrow = g_Eq + cp * Nn;

        for (int i = tid; i < qn; i += TPB) {
            unsigned w = scnt[i];
            if (!w) continue;
            int lq = __ldcg(&g_qlabel[i]);
            if (lq == cp) continue;                  // same-class pairs never used
            float inter = (float)(w & 0xFFFFu);
            float corr  = (float)(w >> 16);
            float sub = degp - inter - corr;
            float arg = (1.0f + S1 * sub) / (1.0f + S1 * inter);
            float v = 1.0f / (1.0f + __expf(arg));   // 1 - sigmoid(arg)
            atomicAdd(&sT[lq],  wp * __ldcg(&eqrow[__ldcg(&g_qlist[i])]) * (v - v0));
            atomicAdd(&sSi[lq], inter);
            atomicAdd(&sSc[lq], corr);
        }
        __syncthreads();
        if (tid < Cc) {
            if (tid != cp) {
                int idx = cp * Cc + tid;
                if (sT[tid]  != 0.f) atomicAdd(&g_T[idx],  sT[tid]);
                if (sSi[tid] != 0.f) atomicAdd(&g_Si[idx], sSi[tid]);
                if (sSc[tid] != 0.f) atomicAdd(&g_Sc[idx], sSc[tid]);
            }
            // this node's role as q: Qs[i][cp] += exp(preds[p,i])
            atomicAdd(&g_Qs[tid * Cc + cp], __ldcg(&g_Eq[tid * Nn + p]));
        }
        if (tid == 0) {
            atomicAdd(&g_Ncnt[cp], 1.f);
            atomicAdd(&g_Sdeg[cp], degp);
            atomicAdd(&g_W0[cp], wp * v0);
        }
        __syncthreads();
    }

    // ===== Barrier 3 + fused final in the last-arriving block =====
    if (tid == 0) { __threadfence(); s_last = (atomicAdd(&g_cnt3, 1) == nblk - 1); }
    __syncthreads();
    if (!s_last) return;
    __threadfence();

    // ce reduction over all 4096 nodes
    float ce = 0.f;
    for (int i = tid; i < Nn; i += TPB) ce += __ldcg(&g_cep[i]);
    sred[tid] = ce;
    __syncthreads();
    for (int o = TPB / 2; o > 0; o >>= 1) {
        if (tid < o) sred[tid] += sred[tid + o];
        __syncthreads();
    }
    float ce_tot = sred[0];
    __syncthreads();

    // one thread per class pair
    float contrib = 0.f;
    if (tid < Cc * Cc) {
        int i = tid / Cc, j = tid - i * Cc;
        if (i != j) {
            float Si = __ldcg(&g_Si[tid]);
            float Ssub = __ldcg(&g_Sdeg[i]) * __ldcg(&g_Ncnt[j]) - Si - __ldcg(&g_Sc[tid]);
            if (Si > 0.f && Ssub > 0.f) {
                float T = __ldcg(&g_T[tid]) + __ldcg(&g_W0[i]) * __ldcg(&g_Qs[tid]);
                float ni = fmaxf(__ldcg(&g_Ncnt[i]), 1.f);
                float nj = fmaxf(__ldcg(&g_Ncnt[j]), 1.f);
                contrib = T / (ni * nj);
            }
        }
    }
    sred[tid] = contrib;
    __syncthreads();
    for (int o = TPB / 2; o > 0; o >>= 1) {
        if (tid < o) sred[tid] += sred[tid + o];
        __syncthreads();
    }
    if (tid == 0) {
        out[0] = ce_tot / (float)Nn + 0.001f * sred[0];
        // reset sync state for the next graph replay (deterministic)
        g_cnt1 = 0; g_cnt2 = 0; g_cnt3 = 0; g_flag1 = 0; g_flag2 = 0;
        __threadfence();
    }
}

// ---------------- launch -----------------------------------------------------
extern "C" void kernel_launch(void* const* d_in, const int* in_sizes, int n_in,
                              void* d_out, int out_size) {
    const float* preds  = (const float*)d_in[0];
    const int*   labels = (const int*)d_in[1];
    const unsigned int* mask = (const unsigned int*)d_in[2];
    const unsigned int* adj  = (const unsigned int*)d_in[3];

    int sms = 148;
    cudaDeviceGetAttribute(&sms, cudaDevAttrMultiProcessorCount, 0);
    int grid = sms * BPS;     // exactly resident: launch_bounds guarantees BPS blocks/SM
    if (grid * TPB < Nn) grid = (Nn + TPB - 1) / TPB;   // safety (never on B200)

    k_fused<<<grid, TPB>>>(preds, labels, mask, adj, (float*)d_out);
}

// round 8
// speedup vs baseline: 1.1515x; 1.1515x over previous
#include <cuda_runtime.h>
#include <stdint.h>

#define Nn 4096
#define Cc 10
#define LMAX 128
#define S1 0.73105857863000489f      // sigmoid(1.0) in fp32
#define TPB 256                       // threads per block
#define BPS 4                         // blocks per SM (forced via launch_bounds)
#define TCAP 2560                     // touched-list capacity

// ---------------- scratch (static device globals; no allocation) ------------
__device__ int   g_colcnt[Nn];            // masked in-neighbor count of column k
__device__ int   g_colidx[Nn * LMAX];     // RANKS of masked in-neighbors of column k
__device__ int   g_deg[Nn];               // out-degree (masked rows only)
__device__ int   g_rowidx[Nn * LMAX];     // out-neighbor node ids (masked rows only)
__device__ unsigned char g_diag[Nn];
__device__ float g_mask[Nn];
__device__ int   g_rank[Nn];              // dense rank among masked nodes, -1 if unmasked
__device__ float g_wp[Nn];                // exp(-pos[p]) * m[p]
__device__ float g_cep[Nn];               // per-node CE contribution
__device__ float g_Eq[Cc * Nn];           // exp(preds[q,i]) * m[q]  (node-indexed)
__device__ float g_EqR[Cc * Nn];          // exp(preds[q,i]), rank-indexed (masked only)
__device__ float g_Qs[Cc * Cc];
__device__ float g_T[Cc * Cc];
__device__ float g_Si[Cc * Cc];
__device__ float g_Sc[Cc * Cc];
__device__ float g_Ncnt[Cc];
__device__ float g_Sdeg[Cc];
__device__ float g_W0[Cc];
__device__ int   g_qn;
__device__ int   g_qlist[Nn];
__device__ int   g_qlabel[Nn];
// software grid barriers (self-resetting at end of each replay)
__device__ int          g_cnt1, g_cnt2, g_cnt3;
__device__ volatile int g_flag1, g_flag2;

__global__ void __launch_bounds__(TPB, BPS)
k_fused(const float* __restrict__ preds,
        const int* __restrict__ labels,
        const unsigned int* __restrict__ mask,
        const unsigned int* __restrict__ adj,
        float* __restrict__ out) {
    __shared__ unsigned int scnt[Nn];         // 16KB rank-indexed counters
    __shared__ int   s_touch[TCAP];           // 10KB touched ranks (this row)
    __shared__ unsigned char slab[Nn];        // 4KB labels by rank
    __shared__ int   s_nbr[LMAX];
    __shared__ float sT[Cc], sSi[Cc], sSc[Cc];
    __shared__ float sred[TPB];
    __shared__ int   s_wsum[TPB / 32];
    __shared__ int   s_last, s_ntouch, s_ovf;

    const int tid = threadIdx.x, bi = blockIdx.x;
    const int lane = tid & 31, wid = tid >> 5;
    const int nblk = gridDim.x;
    const int t = bi * TPB + tid;

    // ================= Phase A: per-node (no atomics) =================
    if (t < Nn) {
        g_colcnt[t] = 0; g_deg[t] = 0; g_diag[t] = 0;
        if (t < Cc * Cc) { g_T[t] = 0.f; g_Si[t] = 0.f; g_Sc[t] = 0.f; g_Qs[t] = 0.f; }
        if (t < Cc) { g_Ncnt[t] = 0.f; g_Sdeg[t] = 0.f; g_W0[t] = 0.f; }

        float m = (mask[t] != 0u) ? 1.f : 0.f;   // 4-byte bool (i32 1 or f32 bits)
        g_mask[t] = m;
        float r[Cc], E[Cc], se = 0.f;
#pragma unroll
        for (int c = 0; c < Cc; c++) {
            r[c] = preds[t * Cc + c];
            E[c] = __expf(r[c]);
            se += E[c];
        }
        int l = labels[t];
        g_cep[t] = __logf(se) - r[l];            // -log softmax[l]
        g_wp[t] = __fdividef(m, E[l]);           // exp(-r[l]) * m
#pragma unroll
        for (int i = 0; i < Cc; i++) g_Eq[i * Nn + t] = E[i] * m;
    }
    // zero the per-block counter array ONCE (touched entries are re-zeroed per row)
    {
        uint4* s4 = (uint4*)scnt;
        for (int i = tid; i < Nn / 4; i += TPB) s4[i] = make_uint4(0, 0, 0, 0);
    }

    // ===== Barrier 1: last-arriving block runs the rank prefix scan =====
    __syncthreads();
    if (tid == 0) { __threadfence(); s_last = (atomicAdd(&g_cnt1, 1) == nblk - 1); }
    __syncthreads();
    if (s_last) {
        __threadfence();
        int base = tid * (Nn / TPB);              // 256 threads x 16 nodes
        unsigned mv = 0; int cnt = 0;
#pragma unroll
        for (int j = 0; j < Nn / TPB; j++) {
            if (__ldcg(&g_mask[base + j]) != 0.f) { mv |= 1u << j; cnt++; }
        }
        int inc = cnt;
#pragma unroll
        for (int o = 1; o < 32; o <<= 1) {
            int y = __shfl_up_sync(0xFFFFFFFFu, inc, o);
            if (lane >= o) inc += y;
        }
        if (lane == 31) s_wsum[wid] = inc;
        __syncthreads();
        int woff = 0;
#pragma unroll
        for (int k = 0; k < TPB / 32; k++) if (k < wid) woff += s_wsum[k];
        int rk = woff + inc - cnt;                // exclusive prefix
#pragma unroll
        for (int j = 0; j < Nn / TPB; j++) {
            int pp = base + j;
            if ((mv >> j) & 1u) {
                g_rank[pp] = rk; g_qlist[rk] = pp; g_qlabel[rk] = labels[pp]; rk++;
            } else g_rank[pp] = -1;
        }
        if (tid == TPB - 1) g_qn = rk;
        __syncthreads();
        if (tid == 0) { __threadfence(); g_flag1 = 1; }
    } else {
        if (tid == 0) { while (g_flag1 == 0) __nanosleep(64); __threadfence(); }
        __syncthreads();
    }
    const int qn = g_qn;                          // first read -> L2, correct

    // ================= Phase B: EqR copy + warp-per-masked-row build =========
    if (t < qn) {                                 // rank-compacted Eq
        int p2 = g_qlist[t];
#pragma unroll
        for (int c = 0; c < Cc; c++) g_EqR[c * Nn + t] = g_Eq[c * Nn + p2];
    }
    {
        int r = bi * (TPB / 32) + wid;            // 8*nblk warps >= qn
        if (r < qn) {
            int p = g_qlist[r];
            const uint4* rowp = (const uint4*)(adj + (size_t)p * Nn);
#pragma unroll
            for (int it = 0; it < 4; it++) {
                uint4 a[8];
#pragma unroll
                for (int s = 0; s < 8; s++) a[s] = rowp[lane + (it * 8 + s) * 32];
#pragma unroll
                for (int s = 0; s < 8; s++) {
                    if (a[s].x | a[s].y | a[s].z | a[s].w) {
                        int i4 = lane + (it * 8 + s) * 32;
                        unsigned parts[4] = {a[s].x, a[s].y, a[s].z, a[s].w};
#pragma unroll
                        for (int u = 0; u < 4; u++) {
                            if (parts[u]) {
                                int kk = i4 * 4 + u;
                                int ri = atomicAdd(&g_deg[p], 1);
                                if (ri < LMAX) g_rowidx[p * LMAX + ri] = kk;
                                int ci = atomicAdd(&g_colcnt[kk], 1);
                                if (ci < LMAX) g_colidx[kk * LMAX + ci] = r;
                                if (p == kk) g_diag[p] = 1;
                            }
                        }
                    }
                }
            }
        }
    }

    // ===== Barrier 2 (full) =====
    __syncthreads();
    if (tid == 0) {
        __threadfence();
        if (atomicAdd(&g_cnt2, 1) == nblk - 1) { __threadfence(); g_flag2 = 1; }
        else { while (g_flag2 == 0) __nanosleep(64); }
        __threadfence();
    }
    __syncthreads();

    // stage labels-by-rank into smem once per block
    for (int i = tid; i < qn; i += TPB) slab[i] = (unsigned char)g_qlabel[i];

    // ================= Phase C: block-per-masked-row pairwise =================
    for (int r = bi; r < qn; r += nblk) {
        int p  = g_qlist[r];
        int cp = (int)0;                           // set below from slab after sync
        if (tid == 0) { s_ntouch = 0; s_ovf = 0; }
        if (tid < Cc) { sT[tid] = 0.f; sSi[tid] = 0.f; sSc[tid] = 0.f; }
        int degi = g_deg[p];
        int dp = min(degi, LMAX);
        for (int i = tid; i < dp; i += TPB) s_nbr[i] = g_rowidx[p * LMAX + i];
        __syncthreads();
        cp = (int)slab[r];

        // expansion: first toucher of a rank appends it to the touched list
        for (int i = wid; i < dp; i += TPB / 32) {
            int k = s_nbr[i];
            int c = min(g_colcnt[k], LMAX);
            const int* cl = g_colidx + k * LMAX;
            for (int j = lane; j < c; j += 32) {
                int rr = cl[j];
                unsigned old = atomicAdd(&scnt[rr], 1u);
                if (old == 0u) {
                    int idx = atomicAdd(&s_ntouch, 1);
                    if (idx < TCAP) s_touch[idx] = rr; else s_ovf = 1;
                }
            }
        }
        for (int i = tid; i < dp; i += TPB) {      // corr bits
            int q = s_nbr[i];
            int rq = g_rank[q];
            if (rq >= 0 && !g_diag[q]) {
                unsigned old = atomicAdd(&scnt[rq], 65536u);
                if (old == 0u) {
                    int idx = atomicAdd(&s_ntouch, 1);
                    if (idx < TCAP) s_touch[idx] = rq; else s_ovf = 1;
                }
            }
        }
        __syncthreads();

        float wp = g_wp[p];
        float degp = (float)degi;
        float v0 = 1.0f / (1.0f + __expf(1.0f + S1 * degp));   // 1 - sigmoid
        const float* eqrow = g_EqR + cp * Nn;                  // rank-indexed

        if (!s_ovf) {
            int nt = s_ntouch;
            for (int j = tid; j < nt; j += TPB) {
                int i = s_touch[j];
                unsigned w = scnt[i];
                scnt[i] = 0u;                       // restore for next row
                int lq = (int)slab[i];
                if (lq == cp) continue;
                float inter = (float)(w & 0xFFFFu);
                float corr  = (float)(w >> 16);
                float sub = degp - inter - corr;
                float arg = (1.0f + S1 * sub) / (1.0f + S1 * inter);
                float v = 1.0f / (1.0f + __expf(arg));
                atomicAdd(&sT[lq],  wp * eqrow[i] * (v - v0));
                atomicAdd(&sSi[lq], inter);
                atomicAdd(&sSc[lq], corr);
            }
        } else {                                    // overflow fallback: full scan
            for (int i = tid; i < qn; i += TPB) {
                unsigned w = scnt[i];
                if (!w) continue;
                scnt[i] = 0u;
                int lq = (int)slab[i];
                if (lq == cp) continue;
                float inter = (float)(w & 0xFFFFu);
                float corr  = (float)(w >> 16);
                float sub = degp - inter - corr;
                float arg = (1.0f + S1 * sub) / (1.0f + S1 * inter);
                float v = 1.0f / (1.0f + __expf(arg));
                atomicAdd(&sT[lq],  wp * eqrow[i] * (v - v0));
                atomicAdd(&sSi[lq], inter);
                atomicAdd(&sSc[lq], corr);
            }
        }
        __syncthreads();
        if (tid < Cc) {
            if (tid != cp) {
                int idx = cp * Cc + tid;
                if (sT[tid]  != 0.f) atomicAdd(&g_T[idx],  sT[tid]);
                if (sSi[tid] != 0.f) atomicAdd(&g_Si[idx], sSi[tid]);
                if (sSc[tid] != 0.f) atomicAdd(&g_Sc[idx], sSc[tid]);
            }
            atomicAdd(&g_Qs[tid * Cc + cp], g_EqR[tid * Nn + r]);   // node as q
        }
        if (tid == 0) {
            atomicAdd(&g_Ncnt[cp], 1.f);
            atomicAdd(&g_Sdeg[cp], degp);
            atomicAdd(&g_W0[cp], wp * v0);
        }
        __syncthreads();
    }

    // ===== Barrier 3 + fused final in the last-arriving block =====
    if (tid == 0) { __threadfence(); s_last = (atomicAdd(&g_cnt3, 1) == nblk - 1); }
    __syncthreads();
    if (!s_last) return;
    __threadfence();

    float ce = 0.f;
    for (int i = tid; i < Nn; i += TPB) ce += g_cep[i];
    sred[tid] = ce;
    __syncthreads();
    for (int o = TPB / 2; o > 0; o >>= 1) {
        if (tid < o) sred[tid] += sred[tid + o];
        __syncthreads();
    }
    float ce_tot = sred[0];
    __syncthreads();

    float contrib = 0.f;
    if (tid < Cc * Cc) {
        int i = tid / Cc, j = tid - i * Cc;
        if (i != j) {
            float Si = g_Si[tid];
            float Ssub = g_Sdeg[i] * g_Ncnt[j] - Si - g_Sc[tid];   // exact ints in f32
            if (Si > 0.f && Ssub > 0.f) {
                float T = g_T[tid] + g_W0[i] * g_Qs[tid];
                float ni = fmaxf(g_Ncnt[i], 1.f);
                float nj = fmaxf(g_Ncnt[j], 1.f);
                contrib = T / (ni * nj);
            }
        }
    }
    sred[tid] = contrib;
    __syncthreads();
    for (int o = TPB / 2; o > 0; o >>= 1) {
        if (tid < o) sred[tid] += sred[tid + o];
        __syncthreads();
    }
    if (tid == 0) {
        out[0] = ce_tot / (float)Nn + 0.001f * sred[0];
        g_cnt1 = 0; g_cnt2 = 0; g_cnt3 = 0; g_flag1 = 0; g_flag2 = 0;
        __threadfence();
    }
}

// ---------------- launch -----------------------------------------------------
extern "C" void kernel_launch(void* const* d_in, const int* in_sizes, int n_in,
                              void* d_out, int out_size) {
    const float* preds  = (const float*)d_in[0];
    const int*   labels = (const int*)d_in[1];
    const unsigned int* mask = (const unsigned int*)d_in[2];
    const unsigned int* adj  = (const unsigned int*)d_in[3];

    int sms = 148;
    cudaDeviceGetAttribute(&sms, cudaDevAttrMultiProcessorCount, 0);
    int grid = sms * BPS;     // exactly resident: launch_bounds guarantees BPS blocks/SM
    if (grid * TPB < Nn) grid = (Nn + TPB - 1) / TPB;   // safety (never on B200)

    k_fused<<<grid, TPB>>>(preds, labels, mask, adj, (float*)d_out);
}

// round 9
// speedup vs baseline: 1.2126x; 1.0530x over previous
#include <cuda_runtime.h>
#include <stdint.h>

#define Nn 4096
#define Cc 10
#define LMAX 128
#define S1 0.73105857863000489f      // sigmoid(1.0) in fp32
#define TPB 256                       // threads per block
#define BPS 4                         // blocks per SM (forced via launch_bounds)
#define TCAP 2560                     // touched-list capacity
#define ABLK (Nn / TPB)               // 16 phase-A blocks
#define SCANBLK ABLK                  // dedicated rank-scan block (runs concurrently)

// ---------------- scratch (static device globals; no allocation) ------------
__device__ int   g_colcnt[Nn];            // masked in-neighbor count of column k (node-indexed)
__device__ int   g_colidx[Nn * LMAX];     // RANKS of masked in-neighbors of column k
__device__ int   g_degR[Nn];              // out-degree, rank-indexed
__device__ int   g_rowidxR[Nn * LMAX];    // out-neighbor NODE ids, rank-indexed
__device__ unsigned char g_diag[Nn];
__device__ int   g_rank[Nn];              // node -> rank (-1 if unmasked)
__device__ float g_wpR[Nn];               // exp(-pos), rank-indexed
__device__ float g_v0R[Nn];               // base v, rank-indexed
__device__ float g_EqR[Cc * Nn];          // exp(preds[q,i]), rank-indexed
__device__ float g_Qs[Cc * Cc];
__device__ float g_T[Cc * Cc];
__device__ float g_Si[Cc * Cc];
__device__ float g_Sc[Cc * Cc];
__device__ float g_Ncnt[Cc];
__device__ float g_Sdeg[Cc];
__device__ float g_W0[Cc];
__device__ float g_cepart[ABLK];          // per-block CE partials (overwritten every run)
__device__ int   g_qn;
__device__ int   g_qlist[Nn];             // rank -> node
__device__ int   g_qlabel[Nn];            // rank -> label
// software sync (self-resetting each replay)
__device__ int          g_cnt1, g_cnt2, g_cnt3;
__device__ volatile int g_flag1, g_flag2;

__global__ void __launch_bounds__(TPB, BPS)
k_fused(const float* __restrict__ preds,
        const int* __restrict__ labels,
        const unsigned int* __restrict__ mask,
        const unsigned int* __restrict__ adj,
        float* __restrict__ out) {
    __shared__ unsigned int scnt[Nn];         // 16KB rank-indexed counters
    __shared__ int   s_touch[TCAP];           // 10KB touched ranks (per row)
    __shared__ unsigned char slab[Nn];        // 4KB labels by rank
    __shared__ int   s_nbr[LMAX];
    __shared__ float sT[Cc], sSi[Cc], sSc[Cc];
    __shared__ float sred[TPB];
    __shared__ int   s_wsum[TPB / 32];
    __shared__ int   s_last, s_ntouch, s_ovf;

    const int tid = threadIdx.x, bi = blockIdx.x;
    const int lane = tid & 31, wid = tid >> 5;
    const int nblk = gridDim.x;
    const int NW = TPB / 32;

    // ============ Phase A (blocks 0..15): zero + CE partial ============
    if (bi < ABLK) {
        int t = bi * TPB + tid;                   // covers [0, Nn)
        g_colcnt[t] = 0; g_degR[t] = 0; g_diag[t] = 0;
        if (t < Cc * Cc) { g_T[t] = 0.f; g_Si[t] = 0.f; g_Sc[t] = 0.f; g_Qs[t] = 0.f; }
        if (t < Cc) { g_Ncnt[t] = 0.f; g_Sdeg[t] = 0.f; g_W0[t] = 0.f; }

        float rl = 0.f, se = 0.f;
        int l = labels[t];
#pragma unroll
        for (int c = 0; c < Cc; c++) {
            float r = preds[t * Cc + c];
            if (c == l) rl = r;
            se += __expf(r);
        }
        float ce = __logf(se) - rl;               // -log softmax[l]
#pragma unroll
        for (int o = 16; o > 0; o >>= 1) ce += __shfl_down_sync(0xFFFFFFFFu, ce, o);
        if (lane == 0) sred[wid] = ce;
        __syncthreads();
        if (tid == 0) {
            float s = 0.f;
#pragma unroll
            for (int w = 0; w < NW; w++) s += sred[w];
            g_cepart[bi] = s;
            __threadfence();
            atomicAdd(&g_cnt1, 1);
        }
    } else if (bi == SCANBLK) {
        // ============ Concurrent rank scan (raw inputs only) ============
        int base = tid * (Nn / TPB);
        unsigned mv = 0; int cnt = 0;
#pragma unroll
        for (int j = 0; j < Nn / TPB; j++) {
            if (mask[base + j] != 0u) { mv |= 1u << j; cnt++; }
        }
        int inc = cnt;
#pragma unroll
        for (int o = 1; o < 32; o <<= 1) {
            int y = __shfl_up_sync(0xFFFFFFFFu, inc, o);
            if (lane >= o) inc += y;
        }
        if (lane == 31) s_wsum[wid] = inc;
        __syncthreads();
        int woff = 0;
#pragma unroll
        for (int k = 0; k < NW; k++) if (k < wid) woff += s_wsum[k];
        int rk = woff + inc - cnt;                // exclusive prefix
#pragma unroll
        for (int j = 0; j < Nn / TPB; j++) {
            int pp = base + j;
            if ((mv >> j) & 1u) {
                g_rank[pp] = rk; g_qlist[rk] = pp; g_qlabel[rk] = labels[pp]; rk++;
            } else g_rank[pp] = -1;
        }
        if (tid == TPB - 1) g_qn = rk;
        __syncthreads();
        if (tid == 0) { __threadfence(); g_flag1 = 1; }
    }

    // ===== Wait: scan done AND all phase-A blocks done =====
    __syncthreads();
    if (tid == 0) {
        while (g_flag1 == 0) __nanosleep(32);
        while (*(volatile int*)&g_cnt1 < ABLK) __nanosleep(32);
        __threadfence();
    }
    __syncthreads();
    const int qn = g_qn;

    // ============ Phase B: warp-per-masked-row, evenly spread ============
    for (int r = bi + nblk * wid; r < qn; r += nblk * NW) {
        int p  = g_qlist[r];
        int lb = g_qlabel[r];
        float e = 0.f;
        if (lane < Cc) {
            e = __expf(preds[p * Cc + lane]);
            g_EqR[lane * Nn + r] = e;
            atomicAdd(&g_Qs[lane * Cc + lb], e);  // node's role as q
        }
        float el = __shfl_sync(0xFFFFFFFFu, e, lb);
        float wpv = __fdividef(1.f, el);          // exp(-pos)
        if (lane == 0) g_wpR[r] = wpv;

        const uint4* rowp = (const uint4*)(adj + (size_t)p * Nn);
        int myc = 0;
#pragma unroll
        for (int it = 0; it < 4; it++) {
            uint4 a[8];
#pragma unroll
            for (int s = 0; s < 8; s++) a[s] = rowp[lane + (it * 8 + s) * 32];
#pragma unroll
            for (int s = 0; s < 8; s++) {
                if (a[s].x | a[s].y | a[s].z | a[s].w) {
                    int i4 = lane + (it * 8 + s) * 32;
                    unsigned parts[4] = {a[s].x, a[s].y, a[s].z, a[s].w};
#pragma unroll
                    for (int u = 0; u < 4; u++) {
                        if (parts[u]) {
                            int kk = i4 * 4 + u;
                            myc++;
                            int ri = atomicAdd(&g_degR[r], 1);
                            if (ri < LMAX) g_rowidxR[r * LMAX + ri] = kk;
                            int ci = atomicAdd(&g_colcnt[kk], 1);
                            if (ci < LMAX) g_colidx[kk * LMAX + ci] = r;
                            if (p == kk) g_diag[p] = 1;
                        }
                    }
                }
            }
        }
#pragma unroll
        for (int o = 16; o > 0; o >>= 1) myc += __shfl_down_sync(0xFFFFFFFFu, myc, o);
        if (lane == 0) {                          // exact degree (warp-local count)
            float degp = (float)myc;
            float v0 = __fdividef(1.f, 1.f + __expf(1.f + S1 * degp));
            g_v0R[r] = v0;
            atomicAdd(&g_Sdeg[lb], degp);
            atomicAdd(&g_W0[lb], wpv * v0);
            atomicAdd(&g_Ncnt[lb], 1.f);
        }
    }

    // zero the per-block smem counters ONCE (touched entries re-zeroed per row)
    {
        uint4* s4 = (uint4*)scnt;
        for (int i = tid; i < Nn / 4; i += TPB) s4[i] = make_uint4(0, 0, 0, 0);
    }

    // ===== Barrier 2 (full) =====
    __syncthreads();
    if (tid == 0) {
        __threadfence();
        if (atomicAdd(&g_cnt2, 1) == nblk - 1) { __threadfence(); g_flag2 = 1; }
        else { while (g_flag2 == 0) __nanosleep(32); }
        __threadfence();
    }
    __syncthreads();

    for (int i = tid; i < qn; i += TPB) slab[i] = (unsigned char)g_qlabel[i];
    __syncthreads();

    // ============ Phase C: block-per-masked-row pairwise ============
    for (int r = bi; r < qn; r += nblk) {
        if (tid == 0) { s_ntouch = 0; s_ovf = 0; }
        if (tid < Cc) { sT[tid] = 0.f; sSi[tid] = 0.f; sSc[tid] = 0.f; }
        int dgi = g_degR[r];
        int dp = min(dgi, LMAX);
        for (int i = tid; i < dp; i += TPB) s_nbr[i] = g_rowidxR[r * LMAX + i];
        __syncthreads();
        int cp = (int)slab[r];

        // expansion with colcnt prefetch pipeline (8 warps)
        {
            int i = wid;
            int k0 = (i < dp) ? s_nbr[i] : -1;
            int c0 = (k0 >= 0) ? g_colcnt[k0] : 0;
            while (i < dp) {
                int inx = i + NW;
                int k1 = (inx < dp) ? s_nbr[inx] : -1;
                int c1 = (k1 >= 0) ? g_colcnt[k1] : 0;   // overlap with current list
                int c = min(c0, LMAX);
                const int* cl = g_colidx + k0 * LMAX;
                for (int j = lane; j < c; j += 32) {
                    int rr = cl[j];
                    unsigned old = atomicAdd(&scnt[rr], 1u);
                    if (old == 0u) {
                        int idx = atomicAdd(&s_ntouch, 1);
                        if (idx < TCAP) s_touch[idx] = rr; else s_ovf = 1;
                    }
                }
                i = inx; k0 = k1; c0 = c1;
            }
        }
        for (int i = tid; i < dp; i += TPB) {      // corr bits
            int q = s_nbr[i];
            int rq = g_rank[q];
            if (rq >= 0 && !g_diag[q]) {
                unsigned old = atomicAdd(&scnt[rq], 65536u);
                if (old == 0u) {
                    int idx = atomicAdd(&s_ntouch, 1);
                    if (idx < TCAP) s_touch[idx] = rq; else s_ovf = 1;
                }
            }
        }
        __syncthreads();

        float wp = g_wpR[r];
        float v0 = g_v0R[r];
        float degp = (float)dgi;
        const float* eqrow = g_EqR + cp * Nn;

        if (!s_ovf) {
            int nt = s_ntouch;
            for (int j = tid; j < nt; j += TPB) {
                int i = s_touch[j];
                unsigned w = scnt[i];
                scnt[i] = 0u;                       // restore for next row
                int lq = (int)slab[i];
                if (lq == cp) continue;
                float inter = (float)(w & 0xFFFFu);
                float corr  = (float)(w >> 16);
                float sub = degp - inter - corr;
                float arg = (1.0f + S1 * sub) / (1.0f + S1 * inter);
                float v = __fdividef(1.0f, 1.0f + __expf(arg));
                atomicAdd(&sT[lq],  wp * eqrow[i] * (v - v0));
                atomicAdd(&sSi[lq], inter);
                atomicAdd(&sSc[lq], corr);
            }
        } else {                                    // overflow fallback: full scan
            for (int i = tid; i < qn; i += TPB) {
                unsigned w = scnt[i];
                if (!w) continue;
                scnt[i] = 0u;
                int lq = (int)slab[i];
                if (lq == cp) continue;
                float inter = (float)(w & 0xFFFFu);
                float corr  = (float)(w >> 16);
                float sub = degp - inter - corr;
                float arg = (1.0f + S1 * sub) / (1.0f + S1 * inter);
                float v = __fdividef(1.0f, 1.0f + __expf(arg));
                atomicAdd(&sT[lq],  wp * eqrow[i] * (v - v0));
                atomicAdd(&sSi[lq], inter);
                atomicAdd(&sSc[lq], corr);
            }
        }
        __syncthreads();
        if (tid < Cc && tid != cp) {
            int idx = cp * Cc + tid;
            if (sT[tid]  != 0.f) atomicAdd(&g_T[idx],  sT[tid]);
            if (sSi[tid] != 0.f) atomicAdd(&g_Si[idx], sSi[tid]);
            if (sSc[tid] != 0.f) atomicAdd(&g_Sc[idx], sSc[tid]);
        }
        __syncthreads();
    }

    // ===== Barrier 3 arrival + fused final in the last block =====
    if (tid == 0) { __threadfence(); s_last = (atomicAdd(&g_cnt3, 1) == nblk - 1); }
    __syncthreads();
    if (!s_last) return;
    __threadfence();

    float ce_tot;
    {
        float ce = 0.f;
        if (tid < ABLK) ce = g_cepart[tid];
        sred[tid] = ce;
        __syncthreads();
        for (int o = TPB / 2; o > 0; o >>= 1) {
            if (tid < o) sred[tid] += sred[tid + o];
            __syncthreads();
        }
        ce_tot = sred[0];
        __syncthreads();
    }

    float contrib = 0.f;
    if (tid < Cc * Cc) {
        int i = tid / Cc, j = tid - i * Cc;
        if (i != j) {
            float Si = g_Si[tid];
            float Ssub = g_Sdeg[i] * g_Ncnt[j] - Si - g_Sc[tid];   // exact ints in f32
            if (Si > 0.f && Ssub > 0.f) {
                float T = g_T[tid] + g_W0[i] * g_Qs[tid];
                float ni = fmaxf(g_Ncnt[i], 1.f);
                float nj = fmaxf(g_Ncnt[j], 1.f);
                contrib = T / (ni * nj);
            }
        }
    }
    sred[tid] = contrib;
    __syncthreads();
    for (int o = TPB / 2; o > 0; o >>= 1) {
        if (tid < o) sred[tid] += sred[tid + o];
        __syncthreads();
    }
    if (tid == 0) {
        out[0] = ce_tot / (float)Nn + 0.001f * sred[0];
        g_cnt1 = 0; g_cnt2 = 0; g_cnt3 = 0; g_flag1 = 0; g_flag2 = 0;
        __threadfence();
    }
}

// ---------------- launch -----------------------------------------------------
extern "C" void kernel_launch(void* const* d_in, const int* in_sizes, int n_in,
                              void* d_out, int out_size) {
    const float* preds  = (const float*)d_in[0];
    const int*   labels = (const int*)d_in[1];
    const unsigned int* mask = (const unsigned int*)d_in[2];
    const unsigned int* adj  = (const unsigned int*)d_in[3];

    int sms = 148;
    cudaDeviceGetAttribute(&sms, cudaDevAttrMultiProcessorCount, 0);
    int grid = sms * BPS;               // fully resident (launch_bounds guarantees)
    if (grid < ABLK + 1) grid = ABLK + 1;   // safety: phase-A blocks + scan block

    k_fused<<<grid, TPB>>>(preds, labels, mask, adj, (float*)d_out);
}

// round 10
// speedup vs baseline: 1.7616x; 1.4528x over previous
#include <cuda_runtime.h>
#include <stdint.h>

#define Nn 4096
#define Cc 10
#define LMAX 128
#define S1 0.73105857863000489f      // sigmoid(1.0) in fp32
#define TCAP 2560

// ---------------- scratch (static device globals; no allocation) ------------
__device__ int   g_colcnt[Nn];            // masked in-neighbor count of column k (node-indexed)
__device__ int   g_colidx[Nn * LMAX];     // RANKS of masked in-neighbors of column k
__device__ int   g_degR[Nn];              // out-degree, rank-indexed
__device__ int   g_rowidxR[Nn * LMAX];    // out-neighbor NODE ids, rank-indexed
__device__ unsigned char g_diag[Nn];      // node has self-loop
__device__ int   g_rank[Nn];              // node -> rank (-1 if unmasked)
__device__ float g_EqR[Cc * Nn];          // exp(preds[q,i]), rank-indexed
__device__ float g_Qs[Cc * Cc];
__device__ float g_T[Cc * Cc];
__device__ float g_Si[Cc * Cc];
__device__ float g_Sc[Cc * Cc];
__device__ float g_Ncnt[Cc];
__device__ float g_Sdeg[Cc];
__device__ float g_W0[Cc];
__device__ float g_cepart[16];            // per-block CE partials (overwritten every run)
__device__ int   g_qn;
__device__ int   g_qlist[Nn];             // rank -> node
__device__ int   g_qlabel[Nn];            // rank -> label
__device__ int   g_done;                  // arrival counter (self-resetting)

// ============ Kernel 1: zero + CE partials (blocks 0-15) ∥ rank scan (block 16)
__global__ void k_prep(const float* __restrict__ preds,
                       const int* __restrict__ labels,
                       const unsigned int* __restrict__ mask) {
    __shared__ float sred[8];
    __shared__ int s_wsum[8];
    int tid = threadIdx.x, bi = blockIdx.x;
    int lane = tid & 31, wid = tid >> 5;

    if (bi < 16) {
        int t = bi * 256 + tid;               // covers [0, Nn)
        g_colcnt[t] = 0; g_degR[t] = 0; g_diag[t] = 0;
        if (t < Cc * Cc) { g_T[t] = 0.f; g_Si[t] = 0.f; g_Sc[t] = 0.f; g_Qs[t] = 0.f; }
        if (t < Cc) { g_Ncnt[t] = 0.f; g_Sdeg[t] = 0.f; g_W0[t] = 0.f; }

        float rl = 0.f, se = 0.f;
        int l = labels[t];
#pragma unroll
        for (int c = 0; c < Cc; c++) {
            float r = preds[t * Cc + c];
            if (c == l) rl = r;
            se += __expf(r);
        }
        float ce = __logf(se) - rl;           // -log softmax[l]
#pragma unroll
        for (int o = 16; o > 0; o >>= 1) ce += __shfl_down_sync(0xFFFFFFFFu, ce, o);
        if (lane == 0) sred[wid] = ce;
        __syncthreads();
        if (tid == 0) {
            float s = 0.f;
#pragma unroll
            for (int w = 0; w < 8; w++) s += sred[w];
            g_cepart[bi] = s;
        }
    } else {
        // rank prefix scan over mask (raw inputs only)
        int base = tid * 16;
        unsigned mv = 0; int cnt = 0;
#pragma unroll
        for (int j = 0; j < 16; j++) {
            if (mask[base + j] != 0u) { mv |= 1u << j; cnt++; }
        }
        int inc = cnt;
#pragma unroll
        for (int o = 1; o < 32; o <<= 1) {
            int y = __shfl_up_sync(0xFFFFFFFFu, inc, o);
            if (lane >= o) inc += y;
        }
        if (lane == 31) s_wsum[wid] = inc;
        __syncthreads();
        int woff = 0;
#pragma unroll
        for (int k = 0; k < 8; k++) if (k < wid) woff += s_wsum[k];
        int rk = woff + inc - cnt;            // exclusive prefix
#pragma unroll
        for (int j = 0; j < 16; j++) {
            int pp = base + j;
            if ((mv >> j) & 1u) {
                g_rank[pp] = rk; g_qlist[rk] = pp; g_qlabel[rk] = labels[pp]; rk++;
            } else g_rank[pp] = -1;
        }
        if (tid == 255) g_qn = rk;
    }
}

// ============ Kernel 2: build — two masked rows per block, high-MLP ============
__device__ __forceinline__ void decode4(uint4 x0, uint4 x1, uint4 x2, uint4 x3,
                                        int tid, int rr, int p) {
    uint4 xs[1];
#pragma unroll
    for (int s = 0; s < 4; s++) {
        uint4 x = (s == 0) ? x0 : (s == 1) ? x1 : (s == 2) ? x2 : x3;
        if (x.x | x.y | x.z | x.w) {
            int i4 = tid + s * 256;
            unsigned parts[4] = {x.x, x.y, x.z, x.w};
#pragma unroll
            for (int u = 0; u < 4; u++) {
                if (parts[u]) {
                    int kk = i4 * 4 + u;
                    int ri = atomicAdd(&g_degR[rr], 1);
                    if (ri < LMAX) g_rowidxR[rr * LMAX + ri] = kk;
                    int ci = atomicAdd(&g_colcnt[kk], 1);
                    if (ci < LMAX) g_colidx[kk * LMAX + ci] = rr;
                    if (p == kk) g_diag[p] = 1;
                }
            }
        }
    }
    (void)xs;
}

__global__ void k_build(const float* __restrict__ preds,
                        const unsigned int* __restrict__ adj) {
    int tid = threadIdx.x, bi = blockIdx.x;
    int qn = g_qn;

    // EqR prologue (blocks 0-7 cover up to 2048 ranks; 8-15 cover 2048-4096)
    if (bi < 16) {
        int t = bi * 256 + tid;
        if (t < qn) {
            int p = g_qlist[t];
#pragma unroll
            for (int c = 0; c < Cc; c++) g_EqR[c * Nn + t] = __expf(preds[p * Cc + c]);
        }
    }

    int r0 = 2 * bi;
    if (r0 >= qn) return;
    bool two = (r0 + 1 < qn);
    int p0 = g_qlist[r0];
    int p1 = two ? g_qlist[r0 + 1] : p0;
    const uint4* row0 = (const uint4*)(adj + (size_t)p0 * Nn);   // 1024 uint4
    const uint4* row1 = (const uint4*)(adj + (size_t)p1 * Nn);

    // issue all 8 loads upfront (MLP=8)
    uint4 a0 = row0[tid], a1 = row0[tid + 256], a2 = row0[tid + 512], a3 = row0[tid + 768];
    uint4 b0 = row1[tid], b1 = row1[tid + 256], b2 = row1[tid + 512], b3 = row1[tid + 768];

    decode4(a0, a1, a2, a3, tid, r0, p0);
    if (two) decode4(b0, b1, b2, b3, tid, r0 + 1, p1);
}

// ============ Kernel 3: one row per block + fused final ============
__global__ void k_process(float* __restrict__ out) {
    __shared__ unsigned int scnt[Nn];         // 16KB rank-indexed counters
    __shared__ int   s_touch[TCAP];           // 10KB touched ranks
    __shared__ int   s_nbr[LMAX];
    __shared__ float sTw[8 * Cc], sSiw[8 * Cc], sScw[8 * Cc];   // per-warp class accum
    __shared__ float sred[256];
    __shared__ int   s_last, s_ntouch, s_ovf;

    const int tid = threadIdx.x, bi = blockIdx.x;
    const int lane = tid & 31, wid = tid >> 5;
    const int qn = g_qn;

    if (bi < qn) {
        const int r = bi;
        if (tid == 0) { s_ntouch = 0; s_ovf = 0; }
        for (int i = tid; i < 8 * Cc; i += 256) { sTw[i] = 0.f; sSiw[i] = 0.f; sScw[i] = 0.f; }
        {   // zero counters (first qn entries)
            int nz = (qn + 3) >> 2;
            uint4* s4 = (uint4*)scnt;
            for (int i = tid; i < nz; i += 256) s4[i] = make_uint4(0, 0, 0, 0);
        }
        int dgi = g_degR[r];
        int dp = min(dgi, LMAX);
        if (tid < dp) s_nbr[tid] = g_rowidxR[r * LMAX + tid];
        __syncthreads();
        int cp = g_qlabel[r];

        // expansion with warp-aggregated touched-list appends
        for (int i = wid; i < dp; i += 8) {
            int k = s_nbr[i];
            int c = min(g_colcnt[k], LMAX);
            const int* cl = g_colidx + k * LMAX;
            for (int jj = 0; jj < c; jj += 32) {
                int j = jj + lane;
                int rr = 0; unsigned old = 1u;
                if (j < c) { rr = cl[j]; old = atomicAdd(&scnt[rr], 1u); }
                unsigned ball = __ballot_sync(0xFFFFFFFFu, old == 0u);
                if (ball) {
                    int leader = __ffs(ball) - 1;
                    int base = 0;
                    if (lane == leader) base = atomicAdd(&s_ntouch, __popc(ball));
                    base = __shfl_sync(0xFFFFFFFFu, base, leader);
                    if (old == 0u) {
                        int off = __popc(ball & ((1u << lane) - 1u));
                        if (base + off < TCAP) s_touch[base + off] = rr; else s_ovf = 1;
                    }
                }
            }
        }
        // corr bits (dp <= 128 -> single predicated step per warp group)
        {
            int rq = 0; unsigned old = 1u;
            if (tid < dp) {
                int q = s_nbr[tid];
                rq = g_rank[q];
                if (rq >= 0 && !g_diag[q]) old = atomicAdd(&scnt[rq], 65536u);
            }
            unsigned ball = __ballot_sync(0xFFFFFFFFu, old == 0u);
            if (ball) {
                int leader = __ffs(ball) - 1;
                int base = 0;
                if (lane == leader) base = atomicAdd(&s_ntouch, __popc(ball));
                base = __shfl_sync(0xFFFFFFFFu, base, leader);
                if (old == 0u) {
                    int off = __popc(ball & ((1u << lane) - 1u));
                    if (base + off < TCAP) s_touch[base + off] = rq; else s_ovf = 1;
                }
            }
        }
        __syncthreads();

        float degp = (float)dgi;
        float wp = __fdividef(1.f, g_EqR[cp * Nn + r]);        // exp(-pos)
        float v0 = __fdividef(1.f, 1.f + __expf(1.f + S1 * degp));
        const float* eqrow = g_EqR + cp * Nn;
        float* myT = sTw + wid * Cc;
        float* mySi = sSiw + wid * Cc;
        float* mySc = sScw + wid * Cc;

        if (!s_ovf) {
            int nt = s_ntouch;
            for (int j = tid; j < nt; j += 256) {
                int i = s_touch[j];
                unsigned w = scnt[i];
                int lq = g_qlabel[i];
                if (lq == cp) continue;
                float inter = (float)(w & 0xFFFFu);
                float corr  = (float)(w >> 16);
                float sub = degp - inter - corr;
                float arg = (1.0f + S1 * sub) / (1.0f + S1 * inter);
                float v = __fdividef(1.0f, 1.0f + __expf(arg));
                atomicAdd(&myT[lq],  wp * eqrow[i] * (v - v0));
                atomicAdd(&mySi[lq], inter);
                atomicAdd(&mySc[lq], corr);
            }
        } else {                                    // overflow fallback: dense scan
            for (int i = tid; i < qn; i += 256) {
                unsigned w = scnt[i];
                if (!w) continue;
                int lq = g_qlabel[i];
                if (lq == cp) continue;
                float inter = (float)(w & 0xFFFFu);
                float corr  = (float)(w >> 16);
                float sub = degp - inter - corr;
                float arg = (1.0f + S1 * sub) / (1.0f + S1 * inter);
                float v = __fdividef(1.0f, 1.0f + __expf(arg));
                atomicAdd(&myT[lq],  wp * eqrow[i] * (v - v0));
                atomicAdd(&mySi[lq], inter);
                atomicAdd(&mySc[lq], corr);
            }
        }
        __syncthreads();
        if (tid < Cc) {
            float tT = 0.f, tSi = 0.f, tSc = 0.f;
#pragma unroll
            for (int w = 0; w < 8; w++) {
                tT += sTw[w * Cc + tid]; tSi += sSiw[w * Cc + tid]; tSc += sScw[w * Cc + tid];
            }
            if (tid != cp) {
                int idx = cp * Cc + tid;
                if (tT  != 0.f) atomicAdd(&g_T[idx],  tT);
                if (tSi != 0.f) atomicAdd(&g_Si[idx], tSi);
                if (tSc != 0.f) atomicAdd(&g_Sc[idx], tSc);
            }
            atomicAdd(&g_Qs[tid * Cc + cp], g_EqR[tid * Nn + r]);   // node as q
        }
        if (tid == 0) {
            atomicAdd(&g_Ncnt[cp], 1.f);
            atomicAdd(&g_Sdeg[cp], degp);
            atomicAdd(&g_W0[cp], wp * v0);
        }
    }

    // ===== arrival + fused final in the last block =====
    __syncthreads();
    if (tid == 0) { __threadfence(); s_last = (atomicAdd(&g_done, 1) == gridDim.x - 1); }
    __syncthreads();
    if (!s_last) return;
    __threadfence();

    float ce = (tid < 16) ? g_cepart[tid] : 0.f;
    sred[tid] = ce;
    __syncthreads();
    for (int o = 128; o > 0; o >>= 1) {
        if (tid < o) sred[tid] += sred[tid + o];
        __syncthreads();
    }
    float ce_tot = sred[0];
    __syncthreads();

    float contrib = 0.f;
    if (tid < Cc * Cc) {
        int i = tid / Cc, j = tid - i * Cc;
        if (i != j) {
            float Si = g_Si[tid];
            float Ssub = g_Sdeg[i] * g_Ncnt[j] - Si - g_Sc[tid];   // exact ints in f32
            if (Si > 0.f && Ssub > 0.f) {
                float T = g_T[tid] + g_W0[i] * g_Qs[tid];
                float ni = fmaxf(g_Ncnt[i], 1.f);
                float nj = fmaxf(g_Ncnt[j], 1.f);
                contrib = T / (ni * nj);
            }
        }
    }
    sred[tid] = contrib;
    __syncthreads();
    for (int o = 128; o > 0; o >>= 1) {
        if (tid < o) sred[tid] += sred[tid + o];
        __syncthreads();
    }
    if (tid == 0) {
        out[0] = ce_tot / (float)Nn + 0.001f * sred[0];
        g_done = 0;                       // reset for next replay (deterministic)
        __threadfence();
    }
}

// ---------------- launch -----------------------------------------------------
extern "C" void kernel_launch(void* const* d_in, const int* in_sizes, int n_in,
                              void* d_out, int out_size) {
    const float* preds  = (const float*)d_in[0];
    const int*   labels = (const int*)d_in[1];
    const unsigned int* mask = (const unsigned int*)d_in[2];
    const unsigned int* adj  = (const unsigned int*)d_in[3];

    k_prep<<<17, 256>>>(preds, labels, mask);
    k_build<<<2048, 256>>>(preds, adj);
    k_process<<<Nn, 256>>>((float*)d_out);
}